// round 3
// baseline (speedup 1.0000x reference)
#include <cuda_runtime.h>

#define LEAK 0.2f
constexpr int B_  = 2;
constexpr int C_  = 16;
constexpr int VOL = 96 * 96 * 96;
constexpr int PLN = 96 * 96;
constexpr int DVF = 48;
constexpr int ZC  = 24;          // z-chunk per block
constexpr int NZC = 96 / ZC;     // 4
constexpr int TILE = 34 * 10;    // halo tile: (32+2) x (8+2)

// Scratch (device globals per harness rules).
__device__ float g_warped[(size_t)B_ * C_ * VOL];  // warped src; later fsum
__device__ float g_corr[(size_t)B_ * 27 * VOL];    // cost volume
__device__ float g_facc[(size_t)B_ * C_ * VOL];    // conv1 accumulator -> f

__device__ __forceinline__ float lrelu(float v) { return v > 0.f ? v : LEAK * v; }

// ---------------------------------------------------------------------------
// K1: trilinear upsample of dvf (48^3 -> 96^3, align_corners) + warp source
// ---------------------------------------------------------------------------
__global__ void warp_kernel(const float* __restrict__ src,
                            const float* __restrict__ dvf)
{
    int idx = blockIdx.x * blockDim.x + threadIdx.x;
    if (idx >= B_ * VOL) return;
    int b = idx / VOL;
    int r = idx - b * VOL;
    int z = r / PLN;
    int y = (r / 96) % 96;
    int x = r % 96;

    const float sc = 47.0f / 95.0f;
    float pz = z * sc, py = y * sc, px = x * sc;
    int z0 = (int)pz, y0 = (int)py, x0 = (int)px;
    int z1 = min(z0 + 1, DVF - 1), y1 = min(y0 + 1, DVF - 1), x1 = min(x0 + 1, DVF - 1);
    float wz = pz - (float)z0, wy = py - (float)y0, wx = px - (float)x0;

    const float* dv = dvf + (size_t)b * 3 * DVF * DVF * DVF;
    float flow[3];
#pragma unroll
    for (int cc = 0; cc < 3; cc++) {
        const float* p = dv + (size_t)cc * DVF * DVF * DVF;
        float v000 = __ldg(p + (z0 * 48 + y0) * 48 + x0);
        float v001 = __ldg(p + (z0 * 48 + y0) * 48 + x1);
        float v010 = __ldg(p + (z0 * 48 + y1) * 48 + x0);
        float v011 = __ldg(p + (z0 * 48 + y1) * 48 + x1);
        float v100 = __ldg(p + (z1 * 48 + y0) * 48 + x0);
        float v101 = __ldg(p + (z1 * 48 + y0) * 48 + x1);
        float v110 = __ldg(p + (z1 * 48 + y1) * 48 + x0);
        float v111 = __ldg(p + (z1 * 48 + y1) * 48 + x1);
        float v00 = v000 * (1.f - wx) + v001 * wx;
        float v01 = v010 * (1.f - wx) + v011 * wx;
        float v10 = v100 * (1.f - wx) + v101 * wx;
        float v11 = v110 * (1.f - wx) + v111 * wx;
        float v0 = v00 * (1.f - wy) + v01 * wy;
        float v1 = v10 * (1.f - wy) + v11 * wy;
        flow[cc] = v0 * (1.f - wz) + v1 * wz;
    }

    float zc = (float)z + flow[0];
    float yc = (float)y + flow[1];
    float xc = (float)x + flow[2];
    float zf = floorf(zc), yf = floorf(yc), xf = floorf(xc);
    float fz = zc - zf, fy = yc - yf, fx = xc - xf;
    int iz0 = (int)zf, iy0 = (int)yf, ix0 = (int)xf;

    int   zi[2] = { iz0, iz0 + 1 };
    int   yi[2] = { iy0, iy0 + 1 };
    int   xi[2] = { ix0, ix0 + 1 };
    float wzv[2] = { 1.f - fz, fz };
    float wyv[2] = { 1.f - fy, fy };
    float wxv[2] = { 1.f - fx, fx };

    int   idx8[8];
    float w8[8];
    int j = 0;
#pragma unroll
    for (int a = 0; a < 2; a++)
#pragma unroll
        for (int bb = 0; bb < 2; bb++)
#pragma unroll
            for (int c2 = 0; c2 < 2; c2++) {
                int zz = zi[a], yy = yi[bb], xx = xi[c2];
                bool valid = (zz >= 0 && zz < 96 && yy >= 0 && yy < 96 &&
                              xx >= 0 && xx < 96);
                int zcl = min(max(zz, 0), 95);
                int ycl = min(max(yy, 0), 95);
                int xcl = min(max(xx, 0), 95);
                idx8[j] = (zcl * 96 + ycl) * 96 + xcl;
                w8[j] = valid ? (wzv[a] * wyv[bb] * wxv[c2]) : 0.f;
                j++;
            }

    const float* sb = src + (size_t)b * C_ * VOL;
    float* ob = g_warped + (size_t)b * C_ * VOL + r;
#pragma unroll
    for (int c = 0; c < C_; c++) {
        const float* sp = sb + (size_t)c * VOL;
        float v = 0.f;
#pragma unroll
        for (int k = 0; k < 8; k++) v = fmaf(w8[k], __ldg(sp + idx8[k]), v);
        ob[(size_t)c * VOL] = v;
    }
}

// ---------------------------------------------------------------------------
// K2: 27-shift cost volume with smem ring of warped planes
// ---------------------------------------------------------------------------
__global__ void __launch_bounds__(256, 3) corrs_kernel(const float* __restrict__ tgt)
{
    extern __shared__ float ring[];   // 3 slots of [16][TILE]
    int bz = blockIdx.z;
    int zc = bz % NZC; bz /= NZC;
    int b = bz;
    int tid = threadIdx.y * 32 + threadIdx.x;
    int tx = threadIdx.x, ty = threadIdx.y;
    int x0 = blockIdx.x * 32, y0 = blockIdx.y * 8;
    int zs = zc * ZC;
    const float* wb = g_warped + (size_t)b * C_ * VOL;

    auto stage = [&](int zp) {
        float* slot = ring + (size_t)(((zp % 3) + 3) % 3) * (C_ * TILE);
        if (zp < 0 || zp > 95) {
            for (int i = tid; i < C_ * TILE; i += 256) slot[i] = 0.f;
        } else {
            const float* pz = wb + (size_t)zp * PLN;
            for (int i = tid; i < C_ * TILE; i += 256) {
                int ci = i / TILE;
                int r = i - ci * TILE;
                int tyy = r / 34;
                int txx = r - tyy * 34;
                int gx = x0 + txx - 1, gy = y0 + tyy - 1;
                float v = 0.f;
                if (gx >= 0 && gx < 96 && gy >= 0 && gy < 96)
                    v = __ldg(pz + (size_t)ci * VOL + gy * 96 + gx);
                slot[i] = v;
            }
        }
    };

    stage(zs - 1);
    stage(zs);
    __syncthreads();

    for (int z = zs; z < zs + ZC; z++) {
        stage(z + 1);
        __syncthreads();

        float t[C_];
        const float* tp = tgt + (size_t)b * C_ * VOL + (size_t)z * PLN +
                          (y0 + ty) * 96 + (x0 + tx);
#pragma unroll
        for (int c = 0; c < C_; c++) t[c] = __ldg(tp + (size_t)c * VOL);

        float* op = g_corr + (size_t)b * 27 * VOL + (size_t)z * PLN +
                    (y0 + ty) * 96 + (x0 + tx);
#pragma unroll
        for (int dz = 0; dz < 3; dz++) {
            const float* sp = ring +
                (size_t)(((z - 1 + dz) % 3 + 3) % 3) * (C_ * TILE) + ty * 34 + tx;
#pragma unroll
            for (int dy = 0; dy < 3; dy++) {
#pragma unroll
                for (int dx = 0; dx < 3; dx++) {
                    const float* q = sp + dy * 34 + dx;
                    float acc = 0.f;
#pragma unroll
                    for (int c = 0; c < C_; c++)
                        acc = fmaf(t[c], q[c * TILE], acc);
                    op[(size_t)(dz * 9 + dy * 3 + dx) * VOL] = lrelu(acc * 0.0625f);
                }
            }
        }
        __syncthreads();
    }
}

// ---------------------------------------------------------------------------
// z-ring 3x3x3 conv with smem plane staging.
// Block: 32x8 output tile, ZC z-chunk, one COUT group of COG.
// ---------------------------------------------------------------------------
template<int CIN, int CIN_TOT, int COUT_TOT, int COG, bool INIT, bool ACT, bool RES>
__global__ void __launch_bounds__(256, 3) convs_kernel(
    const float* __restrict__ in, int ci_off,
    const float* __restrict__ w, const float* __restrict__ bias,
    float* __restrict__ out, const float* __restrict__ res)
{
    constexpr int NCG = COUT_TOT / COG;
    extern __shared__ float smem[];
    float* swgt  = smem;                    // [ci][tap(9)][kz(3)][co]
    float* stile = smem + CIN * 27 * COG;   // [ci][TILE]

    int bz = blockIdx.z;
    int zc = bz % NZC; bz /= NZC;
    int cg = bz % NCG; bz /= NCG;
    int b  = bz;
    int co0 = cg * COG;

    int tid = threadIdx.y * 32 + threadIdx.x;
    int tx = threadIdx.x, ty = threadIdx.y;
    int x0 = blockIdx.x * 32, y0 = blockIdx.y * 8;
    int zs = zc * ZC;

    for (int i = tid; i < CIN * 27 * COG; i += 256) {
        int co = i % COG;
        int r  = i / COG;
        int kz = r % 3; r /= 3;
        int t  = r % 9;
        int ci = r / 9;
        swgt[i] = __ldg(&w[((size_t)(co0 + co) * CIN_TOT + ci_off + ci) * 27 + kz * 9 + t]);
    }

    const float* ib = in + (size_t)b * CIN * VOL;
    size_t out_base = ((size_t)b * COUT_TOT + co0) * VOL + (y0 + ty) * 96 + (x0 + tx);

    float bco[COG];
#pragma unroll
    for (int co = 0; co < COG; co++) bco[co] = INIT ? __ldg(bias + co0 + co) : 0.f;

    float a0[COG], a1[COG], a2[COG];
#pragma unroll
    for (int co = 0; co < COG; co++) { a0[co] = 0.f; a1[co] = 0.f; a2[co] = 0.f; }

    // At plane z: AN accumulates out z+1 (kz=0), AC out z (kz=1), AP out z-1 (kz=2).
#define CONV_STEP(ZP, AP, AC, AN)                                              \
    {                                                                          \
        int z = (ZP);                                                          \
        bool ok = (z >= 0 && z <= 95 && z <= zs + ZC);                         \
        __syncthreads();                                                       \
        if (ok) {                                                              \
            const float* pz = ib + (size_t)z * PLN;                            \
            for (int i = tid; i < CIN * TILE; i += 256) {                      \
                int ci = i / TILE;                                             \
                int r  = i - ci * TILE;                                        \
                int tyy = r / 34;                                              \
                int txx = r - tyy * 34;                                        \
                int gx = x0 + txx - 1, gy = y0 + tyy - 1;                      \
                float v = 0.f;                                                 \
                if (gx >= 0 && gx < 96 && gy >= 0 && gy < 96)                  \
                    v = __ldg(pz + (size_t)ci * VOL + gy * 96 + gx);           \
                stile[i] = v;                                                  \
            }                                                                  \
        }                                                                      \
        __syncthreads();                                                       \
        if (ok) {                                                              \
            _Pragma("unroll 1")                                                \
            for (int ci = 0; ci < CIN; ci++) {                                 \
                const float* tp = stile + ci * TILE + ty * 34 + tx;            \
                float v[9];                                                    \
                v[0] = tp[0];  v[1] = tp[1];  v[2] = tp[2];                    \
                v[3] = tp[34]; v[4] = tp[35]; v[5] = tp[36];                   \
                v[6] = tp[68]; v[7] = tp[69]; v[8] = tp[70];                   \
                const float* wp = swgt + ci * 27 * COG;                        \
                _Pragma("unroll")                                              \
                for (int t = 0; t < 9; t++) {                                  \
                    const float* wt = wp + t * 3 * COG;                        \
                    _Pragma("unroll")                                          \
                    for (int co = 0; co < COG; co++)                           \
                        AN[co] = fmaf(v[t], wt[co], AN[co]);                   \
                    _Pragma("unroll")                                          \
                    for (int co = 0; co < COG; co++)                           \
                        AC[co] = fmaf(v[t], wt[COG + co], AC[co]);             \
                    _Pragma("unroll")                                          \
                    for (int co = 0; co < COG; co++)                           \
                        AP[co] = fmaf(v[t], wt[2 * COG + co], AP[co]);         \
                }                                                              \
            }                                                                  \
        }                                                                      \
        int zo = z - 1;                                                        \
        if (zo >= zs && zo < zs + ZC) {                                        \
            float* po = out + out_base + (size_t)zo * PLN;                     \
            _Pragma("unroll")                                                  \
            for (int co = 0; co < COG; co++) {                                 \
                float vv;                                                      \
                if (INIT) vv = AP[co] + bco[co];                               \
                else      vv = po[(size_t)co * VOL] + AP[co];                  \
                if (ACT)  vv = lrelu(vv);                                      \
                if (RES)  vv += __ldg(res + out_base + (size_t)zo * PLN +      \
                                      (size_t)co * VOL);                       \
                po[(size_t)co * VOL] = vv;                                     \
            }                                                                  \
        }                                                                      \
        _Pragma("unroll")                                                      \
        for (int co = 0; co < COG; co++) AP[co] = 0.f;                         \
    }

    for (int zb = zs - 1; zb <= zs + ZC; zb += 3) {
        CONV_STEP(zb,     a0, a1, a2);
        CONV_STEP(zb + 1, a1, a2, a0);
        CONV_STEP(zb + 2, a2, a0, a1);
    }
#undef CONV_STEP
}

// ---------------------------------------------------------------------------
extern "C" void kernel_launch(void* const* d_in, const int* in_sizes, int n_in,
                              void* d_out, int out_size)
{
    const float* src = (const float*)d_in[0];
    const float* tgt = (const float*)d_in[1];
    const float* dvf = (const float*)d_in[2];
    const float* w1  = (const float*)d_in[3];
    const float* b1  = (const float*)d_in[4];
    const float* w2  = (const float*)d_in[5];
    const float* b2  = (const float*)d_in[6];
    const float* w3  = (const float*)d_in[7];
    const float* b3  = (const float*)d_in[8];
    float* out = (float*)d_out;

    float* warped = nullptr;
    float* corr   = nullptr;
    float* facc   = nullptr;
    cudaGetSymbolAddress((void**)&warped, g_warped);
    cudaGetSymbolAddress((void**)&corr, g_corr);
    cudaGetSymbolAddress((void**)&facc, g_facc);

    // smem sizes (bytes)
    const int smA = (16 * 27 * 8 + 16 * TILE) * 4;   // 35584
    const int smB = (27 * 27 * 8 + 27 * TILE) * 4;   // 60048
    const int sm3 = (16 * 27 * 3 + 16 * TILE) * 4;   // 26944
    const int smC = 3 * C_ * TILE * 4;               // 65280

    cudaFuncSetAttribute((const void*)&convs_kernel<16, 59, 16, 8, true,  false, false>,
                         cudaFuncAttributeMaxDynamicSharedMemorySize, smA);
    cudaFuncSetAttribute((const void*)&convs_kernel<27, 59, 16, 8, false, false, false>,
                         cudaFuncAttributeMaxDynamicSharedMemorySize, smB);
    cudaFuncSetAttribute((const void*)&convs_kernel<16, 59, 16, 8, false, true,  false>,
                         cudaFuncAttributeMaxDynamicSharedMemorySize, smA);
    cudaFuncSetAttribute((const void*)&convs_kernel<16, 16, 16, 8, true,  true,  true>,
                         cudaFuncAttributeMaxDynamicSharedMemorySize, smA);
    cudaFuncSetAttribute((const void*)&convs_kernel<16, 16, 3, 3, true,  true,  false>,
                         cudaFuncAttributeMaxDynamicSharedMemorySize, sm3);
    cudaFuncSetAttribute((const void*)&corrs_kernel,
                         cudaFuncAttributeMaxDynamicSharedMemorySize, smC);

    int nvox = B_ * VOL;
    warp_kernel<<<(nvox + 255) / 256, 256>>>(src, dvf);

    dim3 blk(32, 8);
    dim3 gcorr(3, 12, NZC * B_);
    corrs_kernel<<<gcorr, blk, smC>>>(tgt);

    dim3 g16(3, 12, NZC * 2 * B_);   // 2 cout-groups of 8
    dim3 g3(3, 12, NZC * 1 * B_);    // 1 cout-group of 3

    // conv1 split over CIN: source(16) init, corr(27) accumulate, target(16) accumulate+act
    convs_kernel<16, 59, 16, 8, true,  false, false>
        <<<g16, blk, smA>>>(src,  0,  w1, b1, facc, nullptr);
    convs_kernel<27, 59, 16, 8, false, false, false>
        <<<g16, blk, smB>>>(corr, 16, w1, b1, facc, nullptr);
    convs_kernel<16, 59, 16, 8, false, true,  false>
        <<<g16, blk, smA>>>(tgt,  43, w1, b1, facc, nullptr);
    // conv2 + residual: fsum = f + lrelu(conv(f)); fsum stored in g_warped
    convs_kernel<16, 16, 16, 8, true,  true,  true>
        <<<g16, blk, smA>>>(facc, 0,  w2, b2, warped, facc);
    // conv3: 16 -> 3
    convs_kernel<16, 16, 3, 3, true,  true,  false>
        <<<g3,  blk, sm3>>>(warped, 0, w3, b3, out, nullptr);
}

// round 4
// speedup vs baseline: 1.1252x; 1.1252x over previous
#include <cuda_runtime.h>

#define LEAK 0.2f
constexpr int B_  = 2;
constexpr int C_  = 16;
constexpr int VOL = 96 * 96 * 96;
constexpr int PLN = 96 * 96;
constexpr int DVF = 48;
constexpr int ZC  = 12;          // z-chunk per block
constexpr int NZC = 96 / ZC;     // 8

typedef unsigned long long pk_t;

// Scratch (device globals per harness rules).
__device__ float g_warped[(size_t)B_ * C_ * VOL];  // warped src; later fsum
__device__ float g_corr[(size_t)B_ * 27 * VOL];    // cost volume
__device__ float g_facc[(size_t)B_ * C_ * VOL];    // conv1 out (f)

__device__ __forceinline__ float lrelu(float v) { return v > 0.f ? v : LEAK * v; }

__device__ __forceinline__ pk_t pack2(float lo, float hi) {
    pk_t r; asm("mov.b64 %0, {%1,%2};" : "=l"(r) : "f"(lo), "f"(hi)); return r;
}
__device__ __forceinline__ void unpack2(pk_t p, float& lo, float& hi) {
    asm("mov.b64 {%0,%1}, %2;" : "=f"(lo), "=f"(hi) : "l"(p));
}
__device__ __forceinline__ pk_t ffma2(pk_t a, pk_t b, pk_t c) {
    pk_t d; asm("fma.rn.f32x2 %0, %1, %2, %3;" : "=l"(d) : "l"(a), "l"(b), "l"(c));
    return d;
}

// ---------------------------------------------------------------------------
// K1: trilinear upsample of dvf (48^3 -> 96^3, align_corners) + warp source
// ---------------------------------------------------------------------------
__global__ void warp_kernel(const float* __restrict__ src,
                            const float* __restrict__ dvf)
{
    int idx = blockIdx.x * blockDim.x + threadIdx.x;
    if (idx >= B_ * VOL) return;
    int b = idx / VOL;
    int r = idx - b * VOL;
    int z = r / PLN;
    int y = (r / 96) % 96;
    int x = r % 96;

    const float sc = 47.0f / 95.0f;
    float pz = z * sc, py = y * sc, px = x * sc;
    int z0 = (int)pz, y0 = (int)py, x0 = (int)px;
    int z1 = min(z0 + 1, DVF - 1), y1 = min(y0 + 1, DVF - 1), x1 = min(x0 + 1, DVF - 1);
    float wz = pz - (float)z0, wy = py - (float)y0, wx = px - (float)x0;

    const float* dv = dvf + (size_t)b * 3 * DVF * DVF * DVF;
    float flow[3];
#pragma unroll
    for (int cc = 0; cc < 3; cc++) {
        const float* p = dv + (size_t)cc * DVF * DVF * DVF;
        float v000 = __ldg(p + (z0 * 48 + y0) * 48 + x0);
        float v001 = __ldg(p + (z0 * 48 + y0) * 48 + x1);
        float v010 = __ldg(p + (z0 * 48 + y1) * 48 + x0);
        float v011 = __ldg(p + (z0 * 48 + y1) * 48 + x1);
        float v100 = __ldg(p + (z1 * 48 + y0) * 48 + x0);
        float v101 = __ldg(p + (z1 * 48 + y0) * 48 + x1);
        float v110 = __ldg(p + (z1 * 48 + y1) * 48 + x0);
        float v111 = __ldg(p + (z1 * 48 + y1) * 48 + x1);
        float v00 = v000 * (1.f - wx) + v001 * wx;
        float v01 = v010 * (1.f - wx) + v011 * wx;
        float v10 = v100 * (1.f - wx) + v101 * wx;
        float v11 = v110 * (1.f - wx) + v111 * wx;
        float v0 = v00 * (1.f - wy) + v01 * wy;
        float v1 = v10 * (1.f - wy) + v11 * wy;
        flow[cc] = v0 * (1.f - wz) + v1 * wz;
    }

    float zc = (float)z + flow[0];
    float yc = (float)y + flow[1];
    float xc = (float)x + flow[2];
    float zf = floorf(zc), yf = floorf(yc), xf = floorf(xc);
    float fz = zc - zf, fy = yc - yf, fx = xc - xf;
    int iz0 = (int)zf, iy0 = (int)yf, ix0 = (int)xf;

    int   zi[2] = { iz0, iz0 + 1 };
    int   yi[2] = { iy0, iy0 + 1 };
    int   xi[2] = { ix0, ix0 + 1 };
    float wzv[2] = { 1.f - fz, fz };
    float wyv[2] = { 1.f - fy, fy };
    float wxv[2] = { 1.f - fx, fx };

    int   idx8[8];
    float w8[8];
    int j = 0;
#pragma unroll
    for (int a = 0; a < 2; a++)
#pragma unroll
        for (int bb = 0; bb < 2; bb++)
#pragma unroll
            for (int c2 = 0; c2 < 2; c2++) {
                int zz = zi[a], yy = yi[bb], xx = xi[c2];
                bool valid = (zz >= 0 && zz < 96 && yy >= 0 && yy < 96 &&
                              xx >= 0 && xx < 96);
                int zcl = min(max(zz, 0), 95);
                int ycl = min(max(yy, 0), 95);
                int xcl = min(max(xx, 0), 95);
                idx8[j] = (zcl * 96 + ycl) * 96 + xcl;
                w8[j] = valid ? (wzv[a] * wyv[bb] * wxv[c2]) : 0.f;
                j++;
            }

    const float* sb = src + (size_t)b * C_ * VOL;
    float* ob = g_warped + (size_t)b * C_ * VOL + r;
#pragma unroll
    for (int c = 0; c < C_; c++) {
        const float* sp = sb + (size_t)c * VOL;
        float v = 0.f;
#pragma unroll
        for (int k = 0; k < 8; k++) v = fmaf(w8[k], __ldg(sp + idx8[k]), v);
        ob[(size_t)c * VOL] = v;
    }
}

// ---------------------------------------------------------------------------
// K2: 27-shift cost volume, f32x2 packed, 2 x per thread
// ---------------------------------------------------------------------------
__global__ void __launch_bounds__(256, 2) corrp_kernel(const float* __restrict__ tgt)
{
    int bz = blockIdx.z;
    int zc = bz % NZC; bz /= NZC;
    int b = bz;
    int tx = threadIdx.x, ty = threadIdx.y;
    int gx = blockIdx.x * 32 + tx * 2;
    int y  = blockIdx.y * 16 + ty;
    int zs = zc * ZC;

    const float* wb = g_warped + (size_t)b * C_ * VOL;
    const float* tb = tgt + (size_t)b * C_ * VOL;

    for (int z = zs; z < zs + ZC; z++) {
        pk_t acc[27];
#pragma unroll
        for (int s = 0; s < 27; s++) acc[s] = 0ull;

#pragma unroll 1
        for (int ch = 0; ch < C_; ch++) {
            pk_t t2 = *(const pk_t*)(tb + (size_t)ch * VOL + (size_t)z * PLN + y * 96 + gx);
#pragma unroll
            for (int dz = 0; dz < 3; dz++) {
                int zz = z + dz - 1;
                bool vz = (zz >= 0 && zz <= 95);
#pragma unroll
                for (int dy = 0; dy < 3; dy++) {
                    int yy = y + dy - 1;
                    bool vr = vz && (yy >= 0 && yy <= 95);
                    const float* pr = wb + (size_t)ch * VOL + (size_t)zz * PLN + yy * 96 + gx;
                    float m0 = 0.f, m1 = 0.f, vl = 0.f, vrv = 0.f;
                    if (vr) {
                        float2 m = __ldg((const float2*)pr);
                        m0 = m.x; m1 = m.y;
                        if (gx > 0)  vl  = __ldg(pr - 1);
                        if (gx < 94) vrv = __ldg(pr + 2);
                    }
                    pk_t pL = pack2(vl, m0);
                    pk_t pC = pack2(m0, m1);
                    pk_t pR = pack2(m1, vrv);
                    int s = dz * 9 + dy * 3;
                    acc[s]     = ffma2(t2, pL, acc[s]);
                    acc[s + 1] = ffma2(t2, pC, acc[s + 1]);
                    acc[s + 2] = ffma2(t2, pR, acc[s + 2]);
                }
            }
        }

        float* op = g_corr + (size_t)b * 27 * VOL + (size_t)z * PLN + y * 96 + gx;
#pragma unroll
        for (int s = 0; s < 27; s++) {
            float lo, hi;
            unpack2(acc[s], lo, hi);
            lo = lrelu(lo * 0.0625f);
            hi = lrelu(hi * 0.0625f);
            *(float2*)(op + (size_t)s * VOL) = make_float2(lo, hi);
        }
    }
}

// ---------------------------------------------------------------------------
// Packed 3x3x3 conv, z-ring, XPT=4 (2 packed pairs), duplicated weights in smem.
// Up to 3 input-channel segments (fused conv1). Always inits from bias.
// Block: (8,32) threads -> 32x32 xy tile, ZC z-chunk, COG couts.
// ---------------------------------------------------------------------------
template<int CIN0, int CIN1, int CIN2, int COUT_TOT, int COG, int COUT_STORE,
         bool RES>
__global__ void __launch_bounds__(256, 2) convp_kernel(
    const float* __restrict__ in0, const float* __restrict__ in1,
    const float* __restrict__ in2,
    const float* __restrict__ w, const float* __restrict__ bias,
    float* __restrict__ out, const float* __restrict__ res)
{
    constexpr int CTOT = CIN0 + CIN1 + CIN2;
    constexpr int NCG  = (COUT_TOT + COG - 1) / COG;
    extern __shared__ char smraw[];
    pk_t* swgt = (pk_t*)smraw;   // [ci][t9][kz3][co] duplicated (w,w)

    int bz = blockIdx.z;
    int zc = bz % NZC; bz /= NZC;
    int cg = bz % NCG; bz /= NCG;
    int b  = bz;
    int co0 = cg * COG;

    int tid = threadIdx.y * 8 + threadIdx.x;
    for (int i = tid; i < CTOT * 27 * COG; i += 256) {
        int co = i % COG;
        int r  = i / COG;
        int kz = r % 3;
        int t  = (r / 3) % 9;
        int ci = r / 27;
        int cog = co0 + co;
        float wv = (cog < COUT_TOT)
            ? __ldg(w + ((size_t)cog * CTOT + ci) * 27 + kz * 9 + t) : 0.f;
        swgt[i] = pack2(wv, wv);
    }
    __syncthreads();

    int gx = blockIdx.x * 32 + threadIdx.x * 4;
    int y  = blockIdx.y * 32 + threadIdx.y;
    int zs = zc * ZC;

    const float* base0 = in0 + (size_t)b * CIN0 * VOL;
    const float* base1 = (CIN1 > 0) ? in1 + (size_t)b * CIN1 * VOL : nullptr;
    const float* base2 = (CIN2 > 0) ? in2 + (size_t)b * CIN2 * VOL : nullptr;

    pk_t bpk[COG];
#pragma unroll
    for (int co = 0; co < COG; co++) {
        float bv = (co0 + co < COUT_TOT) ? __ldg(bias + co0 + co) : 0.f;
        bpk[co] = pack2(bv, bv);
    }

    pk_t a0[2 * COG], a1[2 * COG], a2[2 * COG];
#pragma unroll
    for (int i = 0; i < 2 * COG; i++) { a0[i] = 0ull; a1[i] = 0ull; a2[i] = 0ull; }

    // Process one ci-segment's plane rows into AN/AC/AP (kz=0/1/2).
#define SEG_LOOP(BASE, CINSEG, CIOFF, AP, AC, AN)                              \
    _Pragma("unroll 1")                                                        \
    for (int ci = 0; ci < (CINSEG); ci++) {                                    \
        const float* p = (BASE) + ((size_t)ci) * VOL + (size_t)z * PLN +       \
                         y * 96 + gx;                                          \
        const pk_t* wci = swgt + (size_t)((CIOFF) + ci) * 27 * COG;            \
        _Pragma("unroll")                                                      \
        for (int dy = 0; dy < 3; dy++) {                                       \
            int yy = y + dy - 1;                                               \
            bool vy = (yy >= 0 && yy <= 95);                                   \
            const float* pr = p + (dy - 1) * 96;                               \
            float4 A = make_float4(0.f, 0.f, 0.f, 0.f);                        \
            float vl = 0.f, vr = 0.f;                                          \
            if (vy) {                                                          \
                A = __ldg((const float4*)pr);                                  \
                if (gx > 0)  vl = __ldg(pr - 1);                               \
                if (gx < 92) vr = __ldg(pr + 4);                               \
            }                                                                  \
            pk_t e0 = pack2(A.x, A.y);                                         \
            pk_t e1 = pack2(A.z, A.w);                                         \
            pk_t s0 = pack2(vl, A.x);                                          \
            pk_t s1 = pack2(A.y, A.z);                                         \
            pk_t s2 = pack2(A.w, vr);                                          \
            _Pragma("unroll")                                                  \
            for (int kx = 0; kx < 3; kx++) {                                   \
                pk_t P0 = (kx == 0) ? s0 : (kx == 1) ? e0 : s1;                \
                pk_t P1 = (kx == 0) ? s1 : (kx == 1) ? e1 : s2;                \
                const pk_t* wt = wci + ((dy * 3 + kx) * 3) * COG;              \
                _Pragma("unroll")                                              \
                for (int co = 0; co < COG; co++) {                             \
                    pk_t wv = wt[co];                                          \
                    AN[co]       = ffma2(P0, wv, AN[co]);                      \
                    AN[COG + co] = ffma2(P1, wv, AN[COG + co]);                \
                }                                                              \
                _Pragma("unroll")                                              \
                for (int co = 0; co < COG; co++) {                             \
                    pk_t wv = wt[COG + co];                                    \
                    AC[co]       = ffma2(P0, wv, AC[co]);                      \
                    AC[COG + co] = ffma2(P1, wv, AC[COG + co]);                \
                }                                                              \
                _Pragma("unroll")                                              \
                for (int co = 0; co < COG; co++) {                             \
                    pk_t wv = wt[2 * COG + co];                                \
                    AP[co]       = ffma2(P0, wv, AP[co]);                      \
                    AP[COG + co] = ffma2(P1, wv, AP[COG + co]);                \
                }                                                              \
            }                                                                  \
        }                                                                      \
    }

#define CONV_STEP(ZP, AP, AC, AN)                                              \
    {                                                                          \
        int z = (ZP);                                                          \
        if (z >= 0 && z <= 95 && z <= zs + ZC) {                               \
            SEG_LOOP(base0, CIN0, 0, AP, AC, AN);                              \
            if (CIN1 > 0) { SEG_LOOP(base1, CIN1, CIN0, AP, AC, AN); }         \
            if (CIN2 > 0) { SEG_LOOP(base2, CIN2, CIN0 + CIN1, AP, AC, AN); }  \
        }                                                                      \
        int zo = z - 1;                                                        \
        if (zo >= zs && zo < zs + ZC) {                                        \
            _Pragma("unroll")                                                  \
            for (int co = 0; co < COG; co++) {                                 \
                if (co0 + co < COUT_STORE) {                                   \
                    size_t off = ((size_t)(b * COUT_TOT + co0 + co)) * VOL +   \
                                 (size_t)zo * PLN + y * 96 + gx;               \
                    float o0, o1, o2, o3, blo, bhi;                            \
                    unpack2(bpk[co], blo, bhi);                                \
                    unpack2(AP[co], o0, o1);                                   \
                    unpack2(AP[COG + co], o2, o3);                             \
                    o0 = lrelu(o0 + blo); o1 = lrelu(o1 + bhi);                \
                    o2 = lrelu(o2 + blo); o3 = lrelu(o3 + bhi);                \
                    if (RES) {                                                 \
                        float4 r4 = __ldg((const float4*)(res + off));         \
                        o0 += r4.x; o1 += r4.y; o2 += r4.z; o3 += r4.w;        \
                    }                                                          \
                    *(float4*)(out + off) = make_float4(o0, o1, o2, o3);       \
                }                                                              \
            }                                                                  \
        }                                                                      \
        _Pragma("unroll")                                                      \
        for (int i = 0; i < 2 * COG; i++) AP[i] = 0ull;                        \
    }

    for (int zb = zs - 1; zb <= zs + ZC; zb += 3) {
        CONV_STEP(zb,     a0, a1, a2);
        CONV_STEP(zb + 1, a1, a2, a0);
        CONV_STEP(zb + 2, a2, a0, a1);
    }
#undef CONV_STEP
#undef SEG_LOOP
}

// ---------------------------------------------------------------------------
extern "C" void kernel_launch(void* const* d_in, const int* in_sizes, int n_in,
                              void* d_out, int out_size)
{
    const float* src = (const float*)d_in[0];
    const float* tgt = (const float*)d_in[1];
    const float* dvf = (const float*)d_in[2];
    const float* w1  = (const float*)d_in[3];
    const float* b1  = (const float*)d_in[4];
    const float* w2  = (const float*)d_in[5];
    const float* b2  = (const float*)d_in[6];
    const float* w3  = (const float*)d_in[7];
    const float* b3  = (const float*)d_in[8];
    float* out = (float*)d_out;

    float* warped = nullptr;
    float* corr   = nullptr;
    float* facc   = nullptr;
    cudaGetSymbolAddress((void**)&warped, g_warped);
    cudaGetSymbolAddress((void**)&corr, g_corr);
    cudaGetSymbolAddress((void**)&facc, g_facc);

    const int sm1 = 59 * 27 * 4 * (int)sizeof(pk_t);   // 50976
    const int sm2 = 16 * 27 * 4 * (int)sizeof(pk_t);   // 13824
    const int sm3 = 16 * 27 * 2 * (int)sizeof(pk_t);   //  6912

    cudaFuncSetAttribute((const void*)&convp_kernel<16, 27, 16, 16, 4, 16, false>,
                         cudaFuncAttributeMaxDynamicSharedMemorySize, sm1);
    cudaFuncSetAttribute((const void*)&convp_kernel<16, 0, 0, 16, 4, 16, true>,
                         cudaFuncAttributeMaxDynamicSharedMemorySize, sm2);
    cudaFuncSetAttribute((const void*)&convp_kernel<16, 0, 0, 3, 2, 3, false>,
                         cudaFuncAttributeMaxDynamicSharedMemorySize, sm3);

    int nvox = B_ * VOL;
    warp_kernel<<<(nvox + 255) / 256, 256>>>(src, dvf);

    dim3 cblk(16, 16);
    dim3 cgrd(3, 6, NZC * B_);
    corrp_kernel<<<cgrd, cblk>>>(tgt);

    dim3 blk(8, 32);
    dim3 g1(3, 3, NZC * 4 * B_);   // NCG=4
    dim3 g3(3, 3, NZC * 2 * B_);   // NCG=2

    // conv1 fused over its 3 input segments (src, corr, tgt): 59ch -> 16ch, lrelu
    convp_kernel<16, 27, 16, 16, 4, 16, false>
        <<<g1, blk, sm1>>>(src, corr, tgt, w1, b1, facc, nullptr);
    // conv2 + residual: fsum = f + lrelu(conv(f))
    convp_kernel<16, 0, 0, 16, 4, 16, true>
        <<<g1, blk, sm2>>>(facc, nullptr, nullptr, w2, b2, warped, facc);
    // conv3: 16 -> 3
    convp_kernel<16, 0, 0, 3, 2, 3, false>
        <<<g3, blk, sm3>>>(warped, nullptr, nullptr, w3, b3, out, nullptr);
}